// round 1
// baseline (speedup 1.0000x reference)
#include <cuda_runtime.h>
#include <cuda_bf16.h>

// Problem constants
constexpr int B_ = 2;
constexpr int S_ = 2048;
constexpr int E_ = 1024;
constexpr int H_ = 16;
constexpr int D_ = 64;
constexpr int M_ = B_ * S_;   // 4096 rows

// Scratch (device globals: allocation-free rule)
__device__ float g_Q[B_ * H_ * S_ * D_];   // [B,H,S,D]
__device__ float g_K[B_ * H_ * S_ * D_];
__device__ float g_V[B_ * H_ * S_ * D_];
__device__ float g_C[B_ * S_ * E_];        // attention output, merged heads [B,S,E]

// ---------------------------------------------------------------------------
// 128x128x8 register-tiled SGEMM: out = (A @ W + bias) * scale
// A: [M_,E_] row-major, W: [E_,E_] row-major (in,out).
// MODE 0: write out[m*E_+n] (plain).
// MODE 1: write head-split layout out[((b*H+h)*S+s)*D + d], h=n/64, d=n%64.
// ---------------------------------------------------------------------------
template <int MODE>
__global__ __launch_bounds__(256) void gemm128(
    const float* __restrict__ A, const float* __restrict__ W,
    const float* __restrict__ bias, float* __restrict__ out, float scale)
{
    __shared__ float As[8][128];   // transposed A tile: As[k][m]
    __shared__ float Bs[8][128];   // Bs[k][n]

    const int tid = threadIdx.x;
    const int bm = blockIdx.y * 128;
    const int bn = blockIdx.x * 128;
    const int tx = tid & 15;       // 0..15 -> n sub-tile
    const int ty = tid >> 4;       // 0..15 -> m sub-tile

    const int a_row = tid >> 1;          // 0..127
    const int a_c4  = (tid & 1) * 4;     // 0 or 4
    const int b_row = tid >> 5;          // 0..7
    const int b_c4  = (tid & 31) * 4;    // 0..124

    float acc[8][8];
#pragma unroll
    for (int i = 0; i < 8; i++)
#pragma unroll
        for (int j = 0; j < 8; j++) acc[i][j] = 0.f;

    const float* Aptr = A + (size_t)(bm + a_row) * E_ + a_c4;
    const float* Wptr = W + (size_t)b_row * E_ + bn + b_c4;

    for (int k0 = 0; k0 < E_; k0 += 8) {
        float4 av = *(const float4*)(Aptr + k0);
        float4 bv = *(const float4*)(Wptr + (size_t)k0 * E_);
        As[a_c4 + 0][a_row] = av.x;
        As[a_c4 + 1][a_row] = av.y;
        As[a_c4 + 2][a_row] = av.z;
        As[a_c4 + 3][a_row] = av.w;
        *(float4*)&Bs[b_row][b_c4] = bv;
        __syncthreads();

#pragma unroll
        for (int k = 0; k < 8; k++) {
            float a0[8], b0[8];
            *(float4*)&a0[0] = *(const float4*)&As[k][ty * 8];
            *(float4*)&a0[4] = *(const float4*)&As[k][ty * 8 + 4];
            *(float4*)&b0[0] = *(const float4*)&Bs[k][tx * 8];
            *(float4*)&b0[4] = *(const float4*)&Bs[k][tx * 8 + 4];
#pragma unroll
            for (int i = 0; i < 8; i++)
#pragma unroll
                for (int j = 0; j < 8; j++)
                    acc[i][j] += a0[i] * b0[j];
        }
        __syncthreads();
    }

    // Epilogue: bias + scale + layout
#pragma unroll
    for (int i = 0; i < 8; i++) {
        const int m = bm + ty * 8 + i;
        const int b = m >> 11;           // m / S_
        const int s = m & (S_ - 1);
#pragma unroll
        for (int j = 0; j < 8; j++) {
            const int n = bn + tx * 8 + j;
            float v = (acc[i][j] + bias[n]) * scale;
            if (MODE == 0) {
                out[(size_t)m * E_ + n] = v;
            } else {
                const int h = n >> 6;
                const int d = n & 63;
                out[(size_t)((b * H_ + h) * S_ + s) * D_ + d] = v;
            }
        }
    }
}

// ---------------------------------------------------------------------------
// Causal flash attention, fp32. One block = 64 query rows of one (b,h).
// D=64. Online softmax; 4x4 register tiles for both S=QK^T and O=PV.
// Score scale 0.125 (second 1/sqrt(D); first applied in Q projection).
// ---------------------------------------------------------------------------
__global__ __launch_bounds__(256) void attn64()
{
    extern __shared__ float sm[];
    float (*qs)[65] = (float(*)[65])(sm);               // qs[d][r] (transposed)
    float (*ks)[65] = (float(*)[65])(sm + 64 * 65);     // ks[d][j] (transposed)
    float (*ps)[65] = (float(*)[65])(sm + 2 * 64 * 65); // ps[j][r] (P transposed)
    float (*vs)[64] = (float(*)[64])(sm + 3 * 64 * 65); // vs[j][d] (natural)

    const int tid = threadIdx.x;
    const int tx = tid & 15;          // 0..15: key / d-col groups of 4
    const int ty = tid >> 4;          // 0..15: q-row groups of 4
    const int r0 = ty * 4;
    const int c0 = tx * 4;

    const int bh = blockIdx.y;        // 0..B*H-1
    const int qi = blockIdx.x;        // q tile index
    const int q0 = qi * 64;

    const float* Qb = g_Q + (size_t)bh * S_ * D_;
    const float* Kb = g_K + (size_t)bh * S_ * D_;
    const float* Vb = g_V + (size_t)bh * S_ * D_;

    // Load Q tile transposed (once)
#pragma unroll
    for (int ii = 0; ii < 4; ii++) {
        const int f = tid + ii * 256;         // float4 index 0..1023
        const int r = f >> 4;
        const int d4 = (f & 15) * 4;
        float4 v = *(const float4*)&Qb[(size_t)(q0 + r) * D_ + d4];
        qs[d4 + 0][r] = v.x; qs[d4 + 1][r] = v.y;
        qs[d4 + 2][r] = v.z; qs[d4 + 3][r] = v.w;
    }

    float m_run[4], l_run[4], o[4][4];
#pragma unroll
    for (int i = 0; i < 4; i++) {
        m_run[i] = -1e30f;
        l_run[i] = 0.f;
#pragma unroll
        for (int j = 0; j < 4; j++) o[i][j] = 0.f;
    }

    for (int kt = 0; kt <= qi; kt++) {
        const int k0p = kt * 64;
        __syncthreads();   // previous PV reads done before overwriting ks/vs

        // Load K (transposed) and V (natural) tiles
#pragma unroll
        for (int ii = 0; ii < 4; ii++) {
            const int f = tid + ii * 256;
            const int r = f >> 4;
            const int d4 = (f & 15) * 4;
            float4 kv = *(const float4*)&Kb[(size_t)(k0p + r) * D_ + d4];
            ks[d4 + 0][r] = kv.x; ks[d4 + 1][r] = kv.y;
            ks[d4 + 2][r] = kv.z; ks[d4 + 3][r] = kv.w;
            float4 vv = *(const float4*)&Vb[(size_t)(k0p + r) * D_ + d4];
            *(float4*)&vs[r][d4] = vv;
        }
        __syncthreads();

        // Scores: 4 q-rows x 4 keys per thread
        float sc[4][4];
#pragma unroll
        for (int i = 0; i < 4; i++)
#pragma unroll
            for (int j = 0; j < 4; j++) sc[i][j] = 0.f;

#pragma unroll 8
        for (int d = 0; d < 64; d++) {
            float aa[4], bb[4];
#pragma unroll
            for (int i = 0; i < 4; i++) aa[i] = qs[d][r0 + i];
#pragma unroll
            for (int j = 0; j < 4; j++) bb[j] = ks[d][c0 + j];
#pragma unroll
            for (int i = 0; i < 4; i++)
#pragma unroll
                for (int j = 0; j < 4; j++)
                    sc[i][j] += aa[i] * bb[j];
        }

        // Scale + causal mask
#pragma unroll
        for (int i = 0; i < 4; i++) {
            const int qg = q0 + r0 + i;
#pragma unroll
            for (int j = 0; j < 4; j++) {
                const int kg = k0p + c0 + j;
                sc[i][j] = (kg <= qg) ? sc[i][j] * 0.125f : -1e30f;
            }
        }

        // Online softmax per q row (row stats shared across 16-lane group)
#pragma unroll
        for (int i = 0; i < 4; i++) {
            float mt = fmaxf(fmaxf(sc[i][0], sc[i][1]), fmaxf(sc[i][2], sc[i][3]));
#pragma unroll
            for (int off = 8; off >= 1; off >>= 1)
                mt = fmaxf(mt, __shfl_xor_sync(0xffffffffu, mt, off));
            const float mn = fmaxf(m_run[i], mt);
            const float alpha = __expf(m_run[i] - mn);
            m_run[i] = mn;
            float ls = 0.f;
#pragma unroll
            for (int j = 0; j < 4; j++) {
                sc[i][j] = __expf(sc[i][j] - mn);
                ls += sc[i][j];
            }
#pragma unroll
            for (int off = 8; off >= 1; off >>= 1)
                ls += __shfl_xor_sync(0xffffffffu, ls, off);
            l_run[i] = l_run[i] * alpha + ls;
#pragma unroll
            for (int j = 0; j < 4; j++) o[i][j] *= alpha;
        }

        // Store P transposed
#pragma unroll
        for (int i = 0; i < 4; i++)
#pragma unroll
            for (int j = 0; j < 4; j++)
                ps[c0 + j][r0 + i] = sc[i][j];
        __syncthreads();

        // O += P @ V  (k-dim = 64 keys)
#pragma unroll 8
        for (int kk = 0; kk < 64; kk++) {
            float aa[4], bb[4];
#pragma unroll
            for (int i = 0; i < 4; i++) aa[i] = ps[kk][r0 + i];
#pragma unroll
            for (int j = 0; j < 4; j++) bb[j] = vs[kk][c0 + j];
#pragma unroll
            for (int i = 0; i < 4; i++)
#pragma unroll
                for (int j = 0; j < 4; j++)
                    o[i][j] += aa[i] * bb[j];
        }
    }

    // Epilogue: normalize and write merged-head layout [B,S,E]
    const int b = bh / H_;
    const int h = bh % H_;
#pragma unroll
    for (int i = 0; i < 4; i++) {
        const int s = q0 + r0 + i;
        const float inv = 1.f / l_run[i];
#pragma unroll
        for (int j = 0; j < 4; j++)
            g_C[(size_t)(b * S_ + s) * E_ + h * D_ + c0 + j] = o[i][j] * inv;
    }
}

// ---------------------------------------------------------------------------
extern "C" void kernel_launch(void* const* d_in, const int* in_sizes, int n_in,
                              void* d_out, int out_size)
{
    (void)in_sizes; (void)n_in; (void)out_size;
    const float* query = (const float*)d_in[0];
    const float* key   = (const float*)d_in[1];
    const float* value = (const float*)d_in[2];
    const float* Wq    = (const float*)d_in[3];
    const float* Wk    = (const float*)d_in[4];
    const float* Wv    = (const float*)d_in[5];
    const float* Wo    = (const float*)d_in[6];
    const float* bq    = (const float*)d_in[7];
    const float* bk    = (const float*)d_in[8];
    const float* bv    = (const float*)d_in[9];
    const float* bo    = (const float*)d_in[10];
    // d_in[11] = attn_mask (causal, hardcoded)

    float *gQ, *gK, *gV, *gC;
    cudaGetSymbolAddress((void**)&gQ, g_Q);
    cudaGetSymbolAddress((void**)&gK, g_K);
    cudaGetSymbolAddress((void**)&gV, g_V);
    cudaGetSymbolAddress((void**)&gC, g_C);

    const dim3 gg(E_ / 128, M_ / 128);   // (8, 32)
    constexpr float kScaleQ = 0.125f;    // D^-0.5

    gemm128<1><<<gg, 256>>>(query, Wq, bq, gQ, kScaleQ);
    gemm128<1><<<gg, 256>>>(key,   Wk, bk, gK, 1.0f);
    gemm128<1><<<gg, 256>>>(value, Wv, bv, gV, 1.0f);

    constexpr int kAttnSmem = (3 * 64 * 65 + 64 * 64) * (int)sizeof(float); // 66304 B
    cudaFuncSetAttribute(attn64, cudaFuncAttributeMaxDynamicSharedMemorySize, kAttnSmem);
    attn64<<<dim3(S_ / 64, B_ * H_), 256, kAttnSmem>>>();

    gemm128<0><<<gg, 256>>>(gC, Wo, bo, (float*)d_out, 1.0f);
}

// round 3
// speedup vs baseline: 1.1167x; 1.1167x over previous
#include <cuda_runtime.h>
#include <cuda_bf16.h>

// Problem constants
constexpr int B_ = 2;
constexpr int S_ = 2048;
constexpr int E_ = 1024;
constexpr int H_ = 16;
constexpr int D_ = 64;
constexpr int M_ = B_ * S_;   // 4096 rows

// Scratch (device globals: allocation-free rule)
__device__ float g_Q[B_ * H_ * S_ * D_];   // [B,H,S,D]
__device__ float g_K[B_ * H_ * S_ * D_];
__device__ float g_V[B_ * H_ * S_ * D_];
__device__ float g_C[B_ * S_ * E_];        // attention output, merged heads [B,S,E]

// ---------------------------------------------------------------------------
// Helpers
// ---------------------------------------------------------------------------
static __device__ __forceinline__ unsigned smem_u32(const void* p) {
    unsigned a;
    asm("{ .reg .u64 t; cvta.to.shared.u64 t, %1; cvt.u32.u64 %0, t; }"
        : "=r"(a) : "l"(p));
    return a;
}

static __device__ __forceinline__ void ldsm_x4(
    unsigned& r0, unsigned& r1, unsigned& r2, unsigned& r3, unsigned addr)
{
    asm volatile("ldmatrix.sync.aligned.m8n8.x4.shared.b16 {%0,%1,%2,%3}, [%4];"
                 : "=r"(r0), "=r"(r1), "=r"(r2), "=r"(r3) : "r"(addr));
}
static __device__ __forceinline__ void ldsm_x4_t(
    unsigned& r0, unsigned& r1, unsigned& r2, unsigned& r3, unsigned addr)
{
    asm volatile("ldmatrix.sync.aligned.m8n8.x4.trans.shared.b16 {%0,%1,%2,%3}, [%4];"
                 : "=r"(r0), "=r"(r1), "=r"(r2), "=r"(r3) : "r"(addr));
}

static __device__ __forceinline__ void mma16816(
    float* c, const unsigned* a, const unsigned* b)
{
    asm volatile(
        "mma.sync.aligned.m16n8k16.row.col.f32.bf16.bf16.f32 "
        "{%0,%1,%2,%3}, {%4,%5,%6,%7}, {%8,%9}, {%0,%1,%2,%3};"
        : "+f"(c[0]), "+f"(c[1]), "+f"(c[2]), "+f"(c[3])
        : "r"(a[0]), "r"(a[1]), "r"(a[2]), "r"(a[3]), "r"(b[0]), "r"(b[1]));
}

static __device__ __forceinline__ unsigned b2u(__nv_bfloat162 x) {
    return *reinterpret_cast<unsigned*>(&x);
}

// Split a float4 into hi/lo bf16x4 (3-term product error ~2^-16)
static __device__ __forceinline__ void split4(float4 v, uint2& hi, uint2& lo) {
    __nv_bfloat162 h01 = __floats2bfloat162_rn(v.x, v.y);
    __nv_bfloat162 h23 = __floats2bfloat162_rn(v.z, v.w);
    float2 f01 = __bfloat1622float2(h01);
    float2 f23 = __bfloat1622float2(h23);
    __nv_bfloat162 l01 = __floats2bfloat162_rn(v.x - f01.x, v.y - f01.y);
    __nv_bfloat162 l23 = __floats2bfloat162_rn(v.z - f23.x, v.w - f23.y);
    hi = make_uint2(b2u(h01), b2u(h23));
    lo = make_uint2(b2u(l01), b2u(l23));
}

// ---------------------------------------------------------------------------
// HMMA (mma.sync) 3xbf16 GEMM: out = (A @ W + bias) * scale
// A: [M_,E_] fp32 row-major, W: [E_,E_] fp32 row-major (in,out).
// CTA tile 128x128, K-chunk 64. 8 warps, warp tile 32(m) x 64(n).
// MODE 0: out[m*E_+n]. MODE 1: head-split out[((b*H+h)*S+s)*D + d].
// ---------------------------------------------------------------------------
constexpr int LDA = 72;    // bf16 elems per A smem row (64 + 8 pad) -> 144B rows
constexpr int LDB = 136;   // bf16 elems per B smem row (128 + 8 pad) -> 272B rows
constexpr int OFF_AH = 0;                       // 128*72*2  = 18432
constexpr int OFF_AL = 18432;
constexpr int OFF_BH = 36864;                   // 64*136*2 = 17408
constexpr int OFF_BL = 54272;
constexpr int SMEM_GEMM = 71680;

template <int MODE>
__global__ __launch_bounds__(256) void gemm_mma(
    const float* __restrict__ A, const float* __restrict__ W,
    const float* __restrict__ bias, float* __restrict__ out, float scale)
{
    extern __shared__ __align__(16) char smem[];
    const unsigned sb = smem_u32(smem);
    const int tid = threadIdx.x;
    const int wid = tid >> 5;
    const int lane = tid & 31;
    const int bm = blockIdx.y * 128;
    const int bn = blockIdx.x * 128;
    const int wm = (wid >> 1) * 32;    // warp m offset in CTA tile
    const int wn = (wid & 1) * 64;     // warp n offset

    float acc[2][8][4];
#pragma unroll
    for (int mt = 0; mt < 2; mt++)
#pragma unroll
        for (int nt = 0; nt < 8; nt++)
#pragma unroll
            for (int r = 0; r < 4; r++) acc[mt][nt][r] = 0.f;

    // Precompute ldmatrix lane addresses (constant across chunks)
    // A (.x4 non-trans): row = wm + mt*16 + ((lane>>3)&1)*8 + lane&7 ; col = (lane>>4)*8
    unsigned a_base[2];
#pragma unroll
    for (int mt = 0; mt < 2; mt++) {
        const int row = wm + mt * 16 + ((lane >> 3) & 1) * 8 + (lane & 7);
        const int col = (lane >> 4) * 8;
        a_base[mt] = sb + (unsigned)((row * LDA + col) * 2);
    }
    // B (.x4 trans): row(k) = ((lane>>3)&1)*8 + lane&7 ; col(n) = wn + ng*16 + (lane>>4)*8
    unsigned b_base[4];
#pragma unroll
    for (int ng = 0; ng < 4; ng++) {
        const int row = ((lane >> 3) & 1) * 8 + (lane & 7);
        const int col = wn + ng * 16 + (lane >> 4) * 8;
        b_base[ng] = sb + (unsigned)((row * LDB + col) * 2);
    }

    for (int ch = 0; ch < 16; ch++) {
        const int k0 = ch * 64;
        if (ch > 0) __syncthreads();   // prev chunk's ldmatrix reads complete

        // Load+split A chunk: 128 rows x 64 k (2048 float4, 8/thread)
#pragma unroll
        for (int i = 0; i < 8; i++) {
            const int f = tid + i * 256;
            const int row = f >> 4;
            const int kq = (f & 15) << 2;
            float4 v = *(const float4*)(A + (size_t)(bm + row) * E_ + k0 + kq);
            uint2 hi, lo;
            split4(v, hi, lo);
            const int off = (row * LDA + kq) * 2;
            *(uint2*)(smem + OFF_AH + off) = hi;
            *(uint2*)(smem + OFF_AL + off) = lo;
        }
        // Load+split B chunk: 64 k-rows x 128 n (2048 float4, 8/thread)
#pragma unroll
        for (int i = 0; i < 8; i++) {
            const int f = tid + i * 256;
            const int row = f >> 5;
            const int nq = (f & 31) << 2;
            float4 v = *(const float4*)(W + (size_t)(k0 + row) * E_ + bn + nq);
            uint2 hi, lo;
            split4(v, hi, lo);
            const int off = (row * LDB + nq) * 2;
            *(uint2*)(smem + OFF_BH + off) = hi;
            *(uint2*)(smem + OFF_BL + off) = lo;
        }
        __syncthreads();

#pragma unroll
        for (int ks = 0; ks < 4; ks++) {
            // A fragments (hi & lo) for both m-tiles
            unsigned ahf[2][4], alf[2][4];
#pragma unroll
            for (int mt = 0; mt < 2; mt++) {
                const unsigned aoff = (unsigned)(ks * 16 * 2);  // +16 bf16 cols
                ldsm_x4(ahf[mt][0], ahf[mt][1], ahf[mt][2], ahf[mt][3],
                        a_base[mt] + OFF_AH + aoff);
                ldsm_x4(alf[mt][0], alf[mt][1], alf[mt][2], alf[mt][3],
                        a_base[mt] + OFF_AL + aoff);
            }
#pragma unroll
            for (int ng = 0; ng < 4; ng++) {
                const unsigned boff = (unsigned)(ks * 16 * LDB * 2);  // +16 k-rows
                unsigned bh[4], bl[4];
                ldsm_x4_t(bh[0], bh[1], bh[2], bh[3], b_base[ng] + OFF_BH + boff);
                ldsm_x4_t(bl[0], bl[1], bl[2], bl[3], b_base[ng] + OFF_BL + boff);
#pragma unroll
                for (int sub = 0; sub < 2; sub++) {
                    const int nt = ng * 2 + sub;
#pragma unroll
                    for (int mt = 0; mt < 2; mt++) {
                        mma16816(acc[mt][nt], ahf[mt], &bh[sub * 2]);
                        mma16816(acc[mt][nt], ahf[mt], &bl[sub * 2]);
                        mma16816(acc[mt][nt], alf[mt], &bh[sub * 2]);
                    }
                }
            }
        }
    }

    // Epilogue: c fragment -> global, fused bias+scale
#pragma unroll
    for (int mt = 0; mt < 2; mt++) {
#pragma unroll
        for (int nt = 0; nt < 8; nt++) {
            const int col = bn + wn + nt * 8 + (lane & 3) * 2;
            const float2 bb = *(const float2*)(bias + col);
#pragma unroll
            for (int half = 0; half < 2; half++) {
                const int row = bm + wm + mt * 16 + (lane >> 2) + half * 8;
                float2 o2;
                o2.x = (acc[mt][nt][half * 2 + 0] + bb.x) * scale;
                o2.y = (acc[mt][nt][half * 2 + 1] + bb.y) * scale;
                if (MODE == 0) {
                    *(float2*)(out + (size_t)row * E_ + col) = o2;
                } else {
                    const int b = row >> 11;
                    const int s = row & (S_ - 1);
                    const int h = col >> 6;
                    const int d = col & 63;
                    *(float2*)(out + (size_t)((b * H_ + h) * S_ + s) * D_ + d) = o2;
                }
            }
        }
    }
}

// ---------------------------------------------------------------------------
// Causal flash attention, fp32 SIMT (vectorized LDS). One block = 64 q rows.
// ---------------------------------------------------------------------------
constexpr int PAD = 68;  // row stride in floats: 16B-aligned

__global__ __launch_bounds__(256) void attn64()
{
    extern __shared__ float sm[];
    float (*qs)[PAD] = (float(*)[PAD])(sm);                 // qs[d][r]
    float (*ks)[PAD] = (float(*)[PAD])(sm + 64 * PAD);      // ks[d][j]
    float (*ps)[PAD] = (float(*)[PAD])(sm + 2 * 64 * PAD);  // ps[j][r]
    float (*vs)[64]  = (float(*)[64]) (sm + 3 * 64 * PAD);  // vs[j][d]

    const int tid = threadIdx.x;
    const int tx = tid & 15;
    const int ty = tid >> 4;
    const int r0 = ty * 4;
    const int c0 = tx * 4;

    const int bh = blockIdx.y;
    const int qi = blockIdx.x;
    const int q0 = qi * 64;

    const float* Qb = g_Q + (size_t)bh * S_ * D_;
    const float* Kb = g_K + (size_t)bh * S_ * D_;
    const float* Vb = g_V + (size_t)bh * S_ * D_;

#pragma unroll
    for (int ii = 0; ii < 4; ii++) {
        const int f = tid + ii * 256;
        const int r = f >> 4;
        const int d4 = (f & 15) * 4;
        float4 v = *(const float4*)&Qb[(size_t)(q0 + r) * D_ + d4];
        qs[d4 + 0][r] = v.x; qs[d4 + 1][r] = v.y;
        qs[d4 + 2][r] = v.z; qs[d4 + 3][r] = v.w;
    }

    float m_run[4], l_run[4], o[4][4];
#pragma unroll
    for (int i = 0; i < 4; i++) {
        m_run[i] = -1e30f;
        l_run[i] = 0.f;
#pragma unroll
        for (int j = 0; j < 4; j++) o[i][j] = 0.f;
    }

    for (int kt = 0; kt <= qi; kt++) {
        const int k0p = kt * 64;
        __syncthreads();

#pragma unroll
        for (int ii = 0; ii < 4; ii++) {
            const int f = tid + ii * 256;
            const int r = f >> 4;
            const int d4 = (f & 15) * 4;
            float4 kv = *(const float4*)&Kb[(size_t)(k0p + r) * D_ + d4];
            ks[d4 + 0][r] = kv.x; ks[d4 + 1][r] = kv.y;
            ks[d4 + 2][r] = kv.z; ks[d4 + 3][r] = kv.w;
            float4 vv = *(const float4*)&Vb[(size_t)(k0p + r) * D_ + d4];
            *(float4*)&vs[r][d4] = vv;
        }
        __syncthreads();

        float sc[4][4];
#pragma unroll
        for (int i = 0; i < 4; i++)
#pragma unroll
            for (int j = 0; j < 4; j++) sc[i][j] = 0.f;

#pragma unroll 8
        for (int d = 0; d < 64; d++) {
            const float4 a4 = *(const float4*)&qs[d][r0];
            const float4 b4 = *(const float4*)&ks[d][c0];
            const float aa[4] = {a4.x, a4.y, a4.z, a4.w};
            const float bb[4] = {b4.x, b4.y, b4.z, b4.w};
#pragma unroll
            for (int i = 0; i < 4; i++)
#pragma unroll
                for (int j = 0; j < 4; j++)
                    sc[i][j] += aa[i] * bb[j];
        }

#pragma unroll
        for (int i = 0; i < 4; i++) {
            const int qg = q0 + r0 + i;
#pragma unroll
            for (int j = 0; j < 4; j++) {
                const int kg = k0p + c0 + j;
                sc[i][j] = (kg <= qg) ? sc[i][j] * 0.125f : -1e30f;
            }
        }

#pragma unroll
        for (int i = 0; i < 4; i++) {
            float mt = fmaxf(fmaxf(sc[i][0], sc[i][1]), fmaxf(sc[i][2], sc[i][3]));
#pragma unroll
            for (int off = 8; off >= 1; off >>= 1)
                mt = fmaxf(mt, __shfl_xor_sync(0xffffffffu, mt, off));
            const float mn = fmaxf(m_run[i], mt);
            const float alpha = __expf(m_run[i] - mn);
            m_run[i] = mn;
            float ls = 0.f;
#pragma unroll
            for (int j = 0; j < 4; j++) {
                sc[i][j] = __expf(sc[i][j] - mn);
                ls += sc[i][j];
            }
#pragma unroll
            for (int off = 8; off >= 1; off >>= 1)
                ls += __shfl_xor_sync(0xffffffffu, ls, off);
            l_run[i] = l_run[i] * alpha + ls;
#pragma unroll
            for (int j = 0; j < 4; j++) o[i][j] *= alpha;
        }

#pragma unroll
        for (int i = 0; i < 4; i++)
#pragma unroll
            for (int j = 0; j < 4; j++)
                ps[c0 + j][r0 + i] = sc[i][j];
        __syncthreads();

#pragma unroll 8
        for (int kk = 0; kk < 64; kk++) {
            const float4 a4 = *(const float4*)&ps[kk][r0];
            const float4 b4 = *(const float4*)&vs[kk][c0];
            const float aa[4] = {a4.x, a4.y, a4.z, a4.w};
            const float bb[4] = {b4.x, b4.y, b4.z, b4.w};
#pragma unroll
            for (int i = 0; i < 4; i++)
#pragma unroll
                for (int j = 0; j < 4; j++)
                    o[i][j] += aa[i] * bb[j];
        }
    }

    const int b = bh / H_;
    const int h = bh % H_;
#pragma unroll
    for (int i = 0; i < 4; i++) {
        const int s = q0 + r0 + i;
        const float inv = 1.f / l_run[i];
#pragma unroll
        for (int j = 0; j < 4; j++)
            g_C[(size_t)(b * S_ + s) * E_ + h * D_ + c0 + j] = o[i][j] * inv;
    }
}

// ---------------------------------------------------------------------------
extern "C" void kernel_launch(void* const* d_in, const int* in_sizes, int n_in,
                              void* d_out, int out_size)
{
    (void)in_sizes; (void)n_in; (void)out_size;
    const float* query = (const float*)d_in[0];
    const float* key   = (const float*)d_in[1];
    const float* value = (const float*)d_in[2];
    const float* Wq    = (const float*)d_in[3];
    const float* Wk    = (const float*)d_in[4];
    const float* Wv    = (const float*)d_in[5];
    const float* Wo    = (const float*)d_in[6];
    const float* bq    = (const float*)d_in[7];
    const float* bk    = (const float*)d_in[8];
    const float* bv    = (const float*)d_in[9];
    const float* bo    = (const float*)d_in[10];
    // d_in[11] = attn_mask (causal, hardcoded)

    float *gQ, *gK, *gV, *gC;
    cudaGetSymbolAddress((void**)&gQ, g_Q);
    cudaGetSymbolAddress((void**)&gK, g_K);
    cudaGetSymbolAddress((void**)&gV, g_V);
    cudaGetSymbolAddress((void**)&gC, g_C);

    cudaFuncSetAttribute(gemm_mma<0>, cudaFuncAttributeMaxDynamicSharedMemorySize, SMEM_GEMM);
    cudaFuncSetAttribute(gemm_mma<1>, cudaFuncAttributeMaxDynamicSharedMemorySize, SMEM_GEMM);

    const dim3 gg(E_ / 128, M_ / 128);   // (8, 32)
    constexpr float kScaleQ = 0.125f;    // D^-0.5

    gemm_mma<1><<<gg, 256, SMEM_GEMM>>>(query, Wq, bq, gQ, kScaleQ);
    gemm_mma<1><<<gg, 256, SMEM_GEMM>>>(key,   Wk, bk, gK, 1.0f);
    gemm_mma<1><<<gg, 256, SMEM_GEMM>>>(value, Wv, bv, gV, 1.0f);

    constexpr int kAttnSmem = (3 * 64 * PAD + 64 * 64) * (int)sizeof(float);
    cudaFuncSetAttribute(attn64, cudaFuncAttributeMaxDynamicSharedMemorySize, kAttnSmem);
    attn64<<<dim3(S_ / 64, B_ * H_), 256, kAttnSmem>>>();

    gemm_mma<0><<<gg, 256, SMEM_GEMM>>>(gC, Wo, bo, (float*)d_out, 1.0f);
}

// round 4
// speedup vs baseline: 3.4137x; 3.0569x over previous
#include <cuda_runtime.h>
#include <cuda_bf16.h>

// Problem constants
constexpr int B_ = 2;
constexpr int S_ = 2048;
constexpr int E_ = 1024;
constexpr int H_ = 16;
constexpr int D_ = 64;
constexpr int M_ = B_ * S_;   // 4096 rows

// ---------------------------------------------------------------------------
// Device-global scratch (allocation-free rule)
// ---------------------------------------------------------------------------
__device__ __nv_bfloat16 g_Ah[M_ * E_];    // GEMM A operand split (reused)
__device__ __nv_bfloat16 g_Al[M_ * E_];
__device__ __nv_bfloat16 g_Wh[E_ * E_];    // GEMM W operand split (reused)
__device__ __nv_bfloat16 g_Wl[E_ * E_];
__device__ __nv_bfloat16 g_Qh[B_ * H_ * S_ * D_];  // [B,H,S,D] splits
__device__ __nv_bfloat16 g_Ql[B_ * H_ * S_ * D_];
__device__ __nv_bfloat16 g_Kh[B_ * H_ * S_ * D_];
__device__ __nv_bfloat16 g_Kl[B_ * H_ * S_ * D_];
__device__ __nv_bfloat16 g_Vh[B_ * H_ * S_ * D_];
__device__ __nv_bfloat16 g_Vl[B_ * H_ * S_ * D_];
__device__ __nv_bfloat16 g_Ch[B_ * S_ * E_];       // attn out, merged heads
__device__ __nv_bfloat16 g_Cl[B_ * S_ * E_];

// ---------------------------------------------------------------------------
// Helpers
// ---------------------------------------------------------------------------
static __device__ __forceinline__ unsigned smem_u32(const void* p) {
    unsigned a;
    asm("{ .reg .u64 t; cvta.to.shared.u64 t, %1; cvt.u32.u64 %0, t; }"
        : "=r"(a) : "l"(p));
    return a;
}

static __device__ __forceinline__ void cp16(unsigned d, const void* s) {
    asm volatile("cp.async.cg.shared.global [%0], [%1], 16;" :: "r"(d), "l"(s));
}
#define CP_COMMIT() asm volatile("cp.async.commit_group;" ::: "memory")
template <int N> static __device__ __forceinline__ void cp_wait() {
    asm volatile("cp.async.wait_group %0;" :: "n"(N) : "memory");
}

static __device__ __forceinline__ void ldsm_x4(
    unsigned& r0, unsigned& r1, unsigned& r2, unsigned& r3, unsigned addr)
{
    asm volatile("ldmatrix.sync.aligned.m8n8.x4.shared.b16 {%0,%1,%2,%3}, [%4];"
                 : "=r"(r0), "=r"(r1), "=r"(r2), "=r"(r3) : "r"(addr));
}
static __device__ __forceinline__ void ldsm_x4_t(
    unsigned& r0, unsigned& r1, unsigned& r2, unsigned& r3, unsigned addr)
{
    asm volatile("ldmatrix.sync.aligned.m8n8.x4.trans.shared.b16 {%0,%1,%2,%3}, [%4];"
                 : "=r"(r0), "=r"(r1), "=r"(r2), "=r"(r3) : "r"(addr));
}

static __device__ __forceinline__ void mma4(
    float* c, const unsigned* a, unsigned b0, unsigned b1)
{
    asm volatile(
        "mma.sync.aligned.m16n8k16.row.col.f32.bf16.bf16.f32 "
        "{%0,%1,%2,%3}, {%4,%5,%6,%7}, {%8,%9}, {%0,%1,%2,%3};"
        : "+f"(c[0]), "+f"(c[1]), "+f"(c[2]), "+f"(c[3])
        : "r"(a[0]), "r"(a[1]), "r"(a[2]), "r"(a[3]), "r"(b0), "r"(b1));
}

static __device__ __forceinline__ unsigned b2u(__nv_bfloat162 x) {
    return *reinterpret_cast<unsigned*>(&x);
}

static __device__ __forceinline__ void pack2(float v0, float v1,
                                             unsigned& hi, unsigned& lo) {
    __nv_bfloat162 h = __floats2bfloat162_rn(v0, v1);
    float2 f = __bfloat1622float2(h);
    __nv_bfloat162 l = __floats2bfloat162_rn(v0 - f.x, v1 - f.y);
    hi = b2u(h); lo = b2u(l);
}

// ---------------------------------------------------------------------------
// Split pass: fp32 -> bf16 hi/lo
// ---------------------------------------------------------------------------
__global__ __launch_bounds__(256) void split_pass(
    const float4* __restrict__ in, uint2* __restrict__ hi, uint2* __restrict__ lo,
    int n4)
{
    for (int i = blockIdx.x * blockDim.x + threadIdx.x; i < n4;
         i += gridDim.x * blockDim.x) {
        float4 v = in[i];
        unsigned h0, l0, h1, l1;
        pack2(v.x, v.y, h0, l0);
        pack2(v.z, v.w, h1, l1);
        hi[i] = make_uint2(h0, h1);
        lo[i] = make_uint2(l0, l1);
    }
}

// ---------------------------------------------------------------------------
// HMMA 3xbf16 GEMM on pre-split operands, cp.async 2-stage pipeline.
// A(h/l): [M_,E_] bf16 row-major; W(h/l): [E_,E_] bf16 row-major.
// CTA tile 128x128, K-chunk 64, 8 warps of 32(m) x 64(n).
// MODE 0: outf[m*E_+n] = acc + bias (fp32).
// MODE 1: split((acc+bias)*scale) -> outh/outl at ((b*H+h)*S+s)*64 + d.
// ---------------------------------------------------------------------------
constexpr int GLDA = 144;   // A smem row bytes (64+8 bf16)
constexpr int GLDB = 272;   // B smem row bytes (128+8 bf16)
constexpr int G_AH = 0;                 // 128*144 = 18432
constexpr int G_AL = 18432;
constexpr int G_BH = 36864;             // 64*272 = 17408
constexpr int G_BL = 54272;
constexpr int G_STAGE = 71680;
constexpr int SMEM_GEMM = 143360;

template <int MODE>
__global__ __launch_bounds__(256) void gemm_bf16(
    const __nv_bfloat16* __restrict__ Ah, const __nv_bfloat16* __restrict__ Al,
    const __nv_bfloat16* __restrict__ Wh, const __nv_bfloat16* __restrict__ Wl,
    const float* __restrict__ bias, float scale,
    float* __restrict__ outf,
    __nv_bfloat16* __restrict__ outh, __nv_bfloat16* __restrict__ outl)
{
    extern __shared__ __align__(16) char smem[];
    const unsigned sb = smem_u32(smem);
    const int tid = threadIdx.x;
    const int wid = tid >> 5;
    const int lane = tid & 31;
    const int bm = blockIdx.y * 128;
    const int bn = blockIdx.x * 128;
    const int wm = (wid >> 1) * 32;
    const int wn = (wid & 1) * 64;

    float acc[2][8][4];
#pragma unroll
    for (int mt = 0; mt < 2; mt++)
#pragma unroll
        for (int nt = 0; nt < 8; nt++)
#pragma unroll
            for (int r = 0; r < 4; r++) acc[mt][nt][r] = 0.f;

    auto load_stage = [&](int ch, int st) {
        const unsigned base = sb + st * G_STAGE;
        const int k0 = ch * 64;
#pragma unroll
        for (int i = 0; i < 4; i++) {
            const int idx = tid + i * 256;
            const int row = idx >> 3, chk = idx & 7;
            const size_t go = (size_t)(bm + row) * E_ + k0 + chk * 8;
            cp16(base + G_AH + row * GLDA + chk * 16, Ah + go);
            cp16(base + G_AL + row * GLDA + chk * 16, Al + go);
        }
#pragma unroll
        for (int i = 0; i < 4; i++) {
            const int idx = tid + i * 256;
            const int row = idx >> 4, chk = idx & 15;
            const size_t go = (size_t)(k0 + row) * E_ + bn + chk * 8;
            cp16(base + G_BH + row * GLDB + chk * 16, Wh + go);
            cp16(base + G_BL + row * GLDB + chk * 16, Wl + go);
        }
    };

    // ldmatrix lane address offsets (within a stage)
    unsigned a_off[2];
#pragma unroll
    for (int mt = 0; mt < 2; mt++) {
        const int row = wm + mt * 16 + ((lane >> 3) & 1) * 8 + (lane & 7);
        const int col = (lane >> 4) * 8;
        a_off[mt] = (unsigned)(row * GLDA + col * 2);
    }
    unsigned b_off[4];
#pragma unroll
    for (int ng = 0; ng < 4; ng++) {
        const int row = ((lane >> 3) & 1) * 8 + (lane & 7);
        const int col = wn + ng * 16 + (lane >> 4) * 8;
        b_off[ng] = (unsigned)(row * GLDB + col * 2);
    }

    load_stage(0, 0);
    CP_COMMIT();

    for (int ch = 0; ch < 16; ch++) {
        if (ch > 0) __syncthreads();          // stage being refilled fully read
        if (ch + 1 < 16) {
            load_stage(ch + 1, (ch + 1) & 1);
            CP_COMMIT();
            cp_wait<1>();
        } else {
            cp_wait<0>();
        }
        __syncthreads();
        const unsigned base = sb + (ch & 1) * G_STAGE;

#pragma unroll
        for (int ks = 0; ks < 4; ks++) {
            unsigned ahf[2][4], alf[2][4];
#pragma unroll
            for (int mt = 0; mt < 2; mt++) {
                const unsigned ao = base + a_off[mt] + (unsigned)(ks * 16 * 2);
                ldsm_x4(ahf[mt][0], ahf[mt][1], ahf[mt][2], ahf[mt][3], ao + G_AH);
                ldsm_x4(alf[mt][0], alf[mt][1], alf[mt][2], alf[mt][3], ao + G_AL);
            }
#pragma unroll
            for (int ng = 0; ng < 4; ng++) {
                const unsigned bo = base + b_off[ng] + (unsigned)(ks * 16 * GLDB);
                unsigned bh[4], bl[4];
                ldsm_x4_t(bh[0], bh[1], bh[2], bh[3], bo + G_BH);
                ldsm_x4_t(bl[0], bl[1], bl[2], bl[3], bo + G_BL);
#pragma unroll
                for (int sub = 0; sub < 2; sub++) {
                    const int nt = ng * 2 + sub;
#pragma unroll
                    for (int mt = 0; mt < 2; mt++) {
                        mma4(acc[mt][nt], ahf[mt], bh[sub * 2], bh[sub * 2 + 1]);
                        mma4(acc[mt][nt], ahf[mt], bl[sub * 2], bl[sub * 2 + 1]);
                        mma4(acc[mt][nt], alf[mt], bh[sub * 2], bh[sub * 2 + 1]);
                    }
                }
            }
        }
    }

    // Epilogue
#pragma unroll
    for (int mt = 0; mt < 2; mt++) {
#pragma unroll
        for (int nt = 0; nt < 8; nt++) {
            const int col = bn + wn + nt * 8 + (lane & 3) * 2;
            const float2 bb = *(const float2*)(bias + col);
#pragma unroll
            for (int half = 0; half < 2; half++) {
                const int row = bm + wm + mt * 16 + (lane >> 2) + half * 8;
                const float v0 = (acc[mt][nt][half * 2 + 0] + bb.x) * scale;
                const float v1 = (acc[mt][nt][half * 2 + 1] + bb.y) * scale;
                if (MODE == 0) {
                    *(float2*)(outf + (size_t)row * E_ + col) = make_float2(v0, v1);
                } else {
                    const int b = row >> 11;
                    const int s = row & (S_ - 1);
                    const int h = col >> 6;
                    const int d = col & 63;
                    unsigned hi, lo;
                    pack2(v0, v1, hi, lo);
                    const size_t o = (size_t)((b * H_ + h) * S_ + s) * D_ + d;
                    *(unsigned*)(outh + o) = hi;
                    *(unsigned*)(outl + o) = lo;
                }
            }
        }
    }
}

// ---------------------------------------------------------------------------
// Tensor-core causal flash attention. Block = 64 q-rows (4 warps x m16), D=64.
// Split-bf16: QK = QhKh+QhKl+QlKh; PV = PhVh+PhVl+PlVh.  exp2f on MUFU.
// Writes merged-head output as bf16 hi/lo.
// ---------------------------------------------------------------------------
constexpr int ALD = 144;     // smem row bytes (64+8 bf16)
constexpr int A_QH = 0;                  // 64*144 = 9216
constexpr int A_QL = 9216;
constexpr int A_KV0 = 18432;
constexpr int A_KH = 0, A_KL = 9216, A_VH = 18432, A_VL = 27648;
constexpr int A_STAGE = 36864;
constexpr int SMEM_ATTN = 18432 + 2 * 36864;   // 92160

constexpr float KSC = 0.18033688011112042f;    // 0.125 * log2(e)

__global__ __launch_bounds__(128) void attn_tc(
    const __nv_bfloat16* __restrict__ Qh, const __nv_bfloat16* __restrict__ Ql,
    const __nv_bfloat16* __restrict__ Kh, const __nv_bfloat16* __restrict__ Kl,
    const __nv_bfloat16* __restrict__ Vh, const __nv_bfloat16* __restrict__ Vl,
    __nv_bfloat16* __restrict__ Ch, __nv_bfloat16* __restrict__ Cl)
{
    extern __shared__ __align__(16) char smem[];
    const unsigned sb = smem_u32(smem);
    const int tid = threadIdx.x;
    const int wid = tid >> 5;       // 0..3 -> q rows wid*16..
    const int lane = tid & 31;

    const int bh = blockIdx.y;
    const int qi = blockIdx.x;
    const int q0 = qi * 64;
    const size_t hb = (size_t)bh * S_ * D_;

    auto load_kv = [&](int kt, int st) {
        const unsigned base = sb + A_KV0 + st * A_STAGE;
        const int k0p = kt * 64;
#pragma unroll
        for (int i = 0; i < 4; i++) {
            const int idx = tid + i * 128;
            const int row = idx >> 3, chk = idx & 7;
            const size_t go = hb + (size_t)(k0p + row) * D_ + chk * 8;
            const unsigned so = row * ALD + chk * 16;
            cp16(base + A_KH + so, Kh + go);
            cp16(base + A_KL + so, Kl + go);
            cp16(base + A_VH + so, Vh + go);
            cp16(base + A_VL + so, Vl + go);
        }
    };

    // Q tiles -> smem
#pragma unroll
    for (int i = 0; i < 4; i++) {
        const int idx = tid + i * 128;
        const int row = idx >> 3, chk = idx & 7;
        const size_t go = hb + (size_t)(q0 + row) * D_ + chk * 8;
        const unsigned so = row * ALD + chk * 16;
        cp16(sb + A_QH + so, Qh + go);
        cp16(sb + A_QL + so, Ql + go);
    }
    CP_COMMIT();
    load_kv(0, 0);
    CP_COMMIT();
    cp_wait<1>();   // Q group done
    __syncthreads();

    // Q A-fragments (persistent)
    unsigned qhf[4][4], qlf[4][4];
    {
        const int row = wid * 16 + ((lane >> 3) & 1) * 8 + (lane & 7);
        const int colp = (lane >> 4) * 8;
#pragma unroll
        for (int ks = 0; ks < 4; ks++) {
            const unsigned ao = sb + (unsigned)(row * ALD + (ks * 16 + colp) * 2);
            ldsm_x4(qhf[ks][0], qhf[ks][1], qhf[ks][2], qhf[ks][3], ao + A_QH);
            ldsm_x4(qlf[ks][0], qlf[ks][1], qlf[ks][2], qlf[ks][3], ao + A_QL);
        }
    }

    float o[8][4];
#pragma unroll
    for (int nt = 0; nt < 8; nt++)
#pragma unroll
        for (int r = 0; r < 4; r++) o[nt][r] = 0.f;
    float m2[2] = {-1e30f, -1e30f};
    float l2[2] = {0.f, 0.f};

    // B-fragment lane offsets
    const int kb_row = ((lane >> 4) & 1) * 8 + (lane & 7);   // K: bit4 -> key half
    const int kb_col = ((lane >> 3) & 1) * 8;                // K: bit3 -> k half
    const int vb_row = ((lane >> 3) & 1) * 8 + (lane & 7);   // V: bit3 -> key half
    const int vb_col = ((lane >> 4) & 1) * 8;                // V: bit4 -> d half

    const int row_l = (lane >> 2);        // local row in m16
    const int row0g = q0 + wid * 16 + row_l;
    const int row1g = row0g + 8;

    for (int kt = 0; kt <= qi; kt++) {
        if (kt > 0) __syncthreads();
        if (kt + 1 <= qi) {
            load_kv(kt + 1, (kt + 1) & 1);
            CP_COMMIT();
            cp_wait<1>();
        } else {
            cp_wait<0>();
        }
        __syncthreads();
        const unsigned base = sb + A_KV0 + (kt & 1) * A_STAGE;

        // ---- scores ----
        float sc[8][4];
#pragma unroll
        for (int nt = 0; nt < 8; nt++)
#pragma unroll
            for (int r = 0; r < 4; r++) sc[nt][r] = 0.f;

#pragma unroll
        for (int ks = 0; ks < 4; ks++) {
#pragma unroll
            for (int ntp = 0; ntp < 4; ntp++) {
                const unsigned ko = base +
                    (unsigned)((ntp * 16 + kb_row) * ALD + (ks * 16 + kb_col) * 2);
                unsigned kh[4], kl[4];
                ldsm_x4(kh[0], kh[1], kh[2], kh[3], ko + A_KH);
                ldsm_x4(kl[0], kl[1], kl[2], kl[3], ko + A_KL);
                mma4(sc[2 * ntp],     qhf[ks], kh[0], kh[1]);
                mma4(sc[2 * ntp],     qhf[ks], kl[0], kl[1]);
                mma4(sc[2 * ntp],     qlf[ks], kh[0], kh[1]);
                mma4(sc[2 * ntp + 1], qhf[ks], kh[2], kh[3]);
                mma4(sc[2 * ntp + 1], qhf[ks], kl[2], kl[3]);
                mma4(sc[2 * ntp + 1], qlf[ks], kh[2], kh[3]);
            }
        }

        // ---- scale + causal mask ----
#pragma unroll
        for (int nt = 0; nt < 8; nt++) {
            const int cb = kt * 64 + nt * 8 + 2 * (lane & 3);
            sc[nt][0] = (cb     <= row0g) ? sc[nt][0] * KSC : -1e30f;
            sc[nt][1] = (cb + 1 <= row0g) ? sc[nt][1] * KSC : -1e30f;
            sc[nt][2] = (cb     <= row1g) ? sc[nt][2] * KSC : -1e30f;
            sc[nt][3] = (cb + 1 <= row1g) ? sc[nt][3] * KSC : -1e30f;
        }

        // ---- online softmax ----
        float mt0 = -1e30f, mt1 = -1e30f;
#pragma unroll
        for (int nt = 0; nt < 8; nt++) {
            mt0 = fmaxf(mt0, fmaxf(sc[nt][0], sc[nt][1]));
            mt1 = fmaxf(mt1, fmaxf(sc[nt][2], sc[nt][3]));
        }
        mt0 = fmaxf(mt0, __shfl_xor_sync(0xffffffffu, mt0, 1));
        mt0 = fmaxf(mt0, __shfl_xor_sync(0xffffffffu, mt0, 2));
        mt1 = fmaxf(mt1, __shfl_xor_sync(0xffffffffu, mt1, 1));
        mt1 = fmaxf(mt1, __shfl_xor_sync(0xffffffffu, mt1, 2));

        const float mn0 = fmaxf(m2[0], mt0);
        const float mn1 = fmaxf(m2[1], mt1);
        const float al0 = exp2f(m2[0] - mn0);
        const float al1 = exp2f(m2[1] - mn1);
        m2[0] = mn0; m2[1] = mn1;
        l2[0] *= al0; l2[1] *= al1;
#pragma unroll
        for (int nt = 0; nt < 8; nt++) {
            o[nt][0] *= al0; o[nt][1] *= al0;
            o[nt][2] *= al1; o[nt][3] *= al1;
        }

        float ls0 = 0.f, ls1 = 0.f;
#pragma unroll
        for (int nt = 0; nt < 8; nt++) {
            sc[nt][0] = exp2f(sc[nt][0] - mn0);
            sc[nt][1] = exp2f(sc[nt][1] - mn0);
            sc[nt][2] = exp2f(sc[nt][2] - mn1);
            sc[nt][3] = exp2f(sc[nt][3] - mn1);
            ls0 += sc[nt][0] + sc[nt][1];
            ls1 += sc[nt][2] + sc[nt][3];
        }
        ls0 += __shfl_xor_sync(0xffffffffu, ls0, 1);
        ls0 += __shfl_xor_sync(0xffffffffu, ls0, 2);
        ls1 += __shfl_xor_sync(0xffffffffu, ls1, 1);
        ls1 += __shfl_xor_sync(0xffffffffu, ls1, 2);
        l2[0] += ls0; l2[1] += ls1;

        // ---- PV ----
#pragma unroll
        for (int g = 0; g < 4; g++) {
            unsigned ph[4], pl[4];
            pack2(sc[2 * g][0],     sc[2 * g][1],     ph[0], pl[0]);
            pack2(sc[2 * g][2],     sc[2 * g][3],     ph[1], pl[1]);
            pack2(sc[2 * g + 1][0], sc[2 * g + 1][1], ph[2], pl[2]);
            pack2(sc[2 * g + 1][2], sc[2 * g + 1][3], ph[3], pl[3]);
#pragma unroll
            for (int ntp = 0; ntp < 4; ntp++) {
                const unsigned vo = base +
                    (unsigned)((g * 16 + vb_row) * ALD + (ntp * 16 + vb_col) * 2);
                unsigned vh[4], vl[4];
                ldsm_x4_t(vh[0], vh[1], vh[2], vh[3], vo + A_VH);
                ldsm_x4_t(vl[0], vl[1], vl[2], vl[3], vo + A_VL);
                mma4(o[2 * ntp],     ph, vh[0], vh[1]);
                mma4(o[2 * ntp],     ph, vl[0], vl[1]);
                mma4(o[2 * ntp],     pl, vh[0], vh[1]);
                mma4(o[2 * ntp + 1], ph, vh[2], vh[3]);
                mma4(o[2 * ntp + 1], ph, vl[2], vl[3]);
                mma4(o[2 * ntp + 1], pl, vh[2], vh[3]);
            }
        }
    }

    // ---- epilogue: normalize, split, store merged-head bf16 ----
    const float inv0 = 1.f / l2[0];
    const float inv1 = 1.f / l2[1];
    const int b = bh >> 4;
    const int h = bh & 15;
    const int s0 = q0 + wid * 16 + row_l;
#pragma unroll
    for (int nt = 0; nt < 8; nt++) {
        const int col = h * D_ + nt * 8 + 2 * (lane & 3);
        unsigned hi, lo;
        pack2(o[nt][0] * inv0, o[nt][1] * inv0, hi, lo);
        size_t off = (size_t)(b * S_ + s0) * E_ + col;
        *(unsigned*)(Ch + off) = hi;
        *(unsigned*)(Cl + off) = lo;
        pack2(o[nt][2] * inv1, o[nt][3] * inv1, hi, lo);
        off = (size_t)(b * S_ + s0 + 8) * E_ + col;
        *(unsigned*)(Ch + off) = hi;
        *(unsigned*)(Cl + off) = lo;
    }
}

// ---------------------------------------------------------------------------
extern "C" void kernel_launch(void* const* d_in, const int* in_sizes, int n_in,
                              void* d_out, int out_size)
{
    (void)in_sizes; (void)n_in; (void)out_size;
    const float* query = (const float*)d_in[0];
    const float* key   = (const float*)d_in[1];
    const float* value = (const float*)d_in[2];
    const float* Wq    = (const float*)d_in[3];
    const float* Wk    = (const float*)d_in[4];
    const float* Wv    = (const float*)d_in[5];
    const float* Wo    = (const float*)d_in[6];
    const float* bq    = (const float*)d_in[7];
    const float* bk    = (const float*)d_in[8];
    const float* bv    = (const float*)d_in[9];
    const float* bo    = (const float*)d_in[10];
    // d_in[11] = attn_mask (causal, hardcoded)

    __nv_bfloat16 *Ah, *Al, *Wh, *Wl, *Qh, *Ql, *Kh, *Kl, *Vh, *Vl, *Ch, *Cl;
    cudaGetSymbolAddress((void**)&Ah, g_Ah);
    cudaGetSymbolAddress((void**)&Al, g_Al);
    cudaGetSymbolAddress((void**)&Wh, g_Wh);
    cudaGetSymbolAddress((void**)&Wl, g_Wl);
    cudaGetSymbolAddress((void**)&Qh, g_Qh);
    cudaGetSymbolAddress((void**)&Ql, g_Ql);
    cudaGetSymbolAddress((void**)&Kh, g_Kh);
    cudaGetSymbolAddress((void**)&Kl, g_Kl);
    cudaGetSymbolAddress((void**)&Vh, g_Vh);
    cudaGetSymbolAddress((void**)&Vl, g_Vl);
    cudaGetSymbolAddress((void**)&Ch, g_Ch);
    cudaGetSymbolAddress((void**)&Cl, g_Cl);

    cudaFuncSetAttribute(gemm_bf16<0>, cudaFuncAttributeMaxDynamicSharedMemorySize, SMEM_GEMM);
    cudaFuncSetAttribute(gemm_bf16<1>, cudaFuncAttributeMaxDynamicSharedMemorySize, SMEM_GEMM);
    cudaFuncSetAttribute(attn_tc, cudaFuncAttributeMaxDynamicSharedMemorySize, SMEM_ATTN);

    const int nA4 = M_ * E_ / 4;   // 1M float4
    const int nW4 = E_ * E_ / 4;   // 256K float4
    const dim3 gg(E_ / 128, M_ / 128);   // (8, 32)
    constexpr float kScaleQ = 0.125f;    // D^-0.5

    // Q projection
    split_pass<<<1024, 256>>>((const float4*)query, (uint2*)Ah, (uint2*)Al, nA4);
    split_pass<<<512, 256>>>((const float4*)Wq, (uint2*)Wh, (uint2*)Wl, nW4);
    gemm_bf16<1><<<gg, 256, SMEM_GEMM>>>(Ah, Al, Wh, Wl, bq, kScaleQ, nullptr, Qh, Ql);
    // K projection
    split_pass<<<1024, 256>>>((const float4*)key, (uint2*)Ah, (uint2*)Al, nA4);
    split_pass<<<512, 256>>>((const float4*)Wk, (uint2*)Wh, (uint2*)Wl, nW4);
    gemm_bf16<1><<<gg, 256, SMEM_GEMM>>>(Ah, Al, Wh, Wl, bk, 1.0f, nullptr, Kh, Kl);
    // V projection
    split_pass<<<1024, 256>>>((const float4*)value, (uint2*)Ah, (uint2*)Al, nA4);
    split_pass<<<512, 256>>>((const float4*)Wv, (uint2*)Wh, (uint2*)Wl, nW4);
    gemm_bf16<1><<<gg, 256, SMEM_GEMM>>>(Ah, Al, Wh, Wl, bv, 1.0f, nullptr, Vh, Vl);

    // Attention
    attn_tc<<<dim3(S_ / 64, B_ * H_), 128, SMEM_ATTN>>>(Qh, Ql, Kh, Kl, Vh, Vl, Ch, Cl);

    // Output projection (fp32 out)
    split_pass<<<512, 256>>>((const float4*)Wo, (uint2*)Wh, (uint2*)Wl, nW4);
    gemm_bf16<0><<<gg, 256, SMEM_GEMM>>>(Ch, Cl, Wh, Wl, bo, 1.0f, (float*)d_out, nullptr, nullptr);
}